// round 1
// baseline (speedup 1.0000x reference)
#include <cuda_runtime.h>
#include <cuda_bf16.h>
#include <math.h>

// ContrastiveLoss: loss = sum_i [ logsumexp_j(S_ij) - S_ii ],  S = X @ Y^T / TEMP
// N = 8192, C = 512, TEMP = 0.07. Work in log2 domain: score = dot * (1/T)*log2(e).

#define NROWS 8192
#define CDIM  512
#define BM 128
#define BN 128
#define BK 16
#define COLSPLIT 4
#define COLS_PER_SPLIT (NROWS / COLSPLIT)   // 2048
#define TILES_PER_SPLIT (COLS_PER_SPLIT / BN) // 16

// log2-domain scale: (1/0.07) * log2(e)
#define SCALE_LOG2 (14.285714285714286f * 1.4426950408889634f)
#define LN2 0.6931471805599453f

// scratch (device globals; no allocation allowed)
__device__ float g_m[COLSPLIT][NROWS];
__device__ float g_l[COLSPLIT][NROWS];
__device__ float g_pos[NROWS];   // diagonal score, log2 domain
__device__ float g_row[NROWS];   // per-row (lse2 - pos2), log2 domain

__device__ __forceinline__ float ex2f(float x) {
    float y;
    asm("ex2.approx.ftz.f32 %0, %1;" : "=f"(y) : "f"(x));
    return y;
}

__global__ void __launch_bounds__(256, 2)
cl_main_kernel(const float* __restrict__ X, const float* __restrict__ Y) {
    const int row0 = blockIdx.x * BM;                  // 0..8064
    const int split = blockIdx.y;                      // 0..3
    const int col_base = split * COLS_PER_SPLIT;

    __shared__ __align__(16) float Xs[BK][BM];
    __shared__ __align__(16) float Ys[BK][BN];

    const int tid = threadIdx.x;
    const int tx = tid & 15;   // column group (8 cols each)
    const int ty = tid >> 4;   // row group    (8 rows each)

    float m[8], l[8];
#pragma unroll
    for (int r = 0; r < 8; r++) { m[r] = -INFINITY; l[r] = 0.0f; }

    for (int ct = 0; ct < TILES_PER_SPLIT; ct++) {
        const int col0 = col_base + ct * BN;

        float acc[8][8];
#pragma unroll
        for (int r = 0; r < 8; r++)
#pragma unroll
            for (int c = 0; c < 8; c++) acc[r][c] = 0.0f;

        for (int k0 = 0; k0 < CDIM; k0 += BK) {
            // load 128x16 tiles of X and Y (k-major in smem)
#pragma unroll
            for (int s = tid; s < (BM * BK) / 4; s += 256) {
                const int row = s >> 2;
                const int kq = s & 3;
                float4 v = *reinterpret_cast<const float4*>(
                    X + (size_t)(row0 + row) * CDIM + k0 + kq * 4);
                Xs[kq * 4 + 0][row] = v.x;
                Xs[kq * 4 + 1][row] = v.y;
                Xs[kq * 4 + 2][row] = v.z;
                Xs[kq * 4 + 3][row] = v.w;
                float4 w = *reinterpret_cast<const float4*>(
                    Y + (size_t)(col0 + row) * CDIM + k0 + kq * 4);
                Ys[kq * 4 + 0][row] = w.x;
                Ys[kq * 4 + 1][row] = w.y;
                Ys[kq * 4 + 2][row] = w.z;
                Ys[kq * 4 + 3][row] = w.w;
            }
            __syncthreads();

#pragma unroll
            for (int kk = 0; kk < BK; kk++) {
                float4 xa = *reinterpret_cast<const float4*>(&Xs[kk][ty * 8]);
                float4 xb = *reinterpret_cast<const float4*>(&Xs[kk][ty * 8 + 4]);
                float4 ya = *reinterpret_cast<const float4*>(&Ys[kk][tx * 8]);
                float4 yb = *reinterpret_cast<const float4*>(&Ys[kk][tx * 8 + 4]);
                float xf[8] = {xa.x, xa.y, xa.z, xa.w, xb.x, xb.y, xb.z, xb.w};
                float yf[8] = {ya.x, ya.y, ya.z, ya.w, yb.x, yb.y, yb.z, yb.w};
#pragma unroll
                for (int r = 0; r < 8; r++)
#pragma unroll
                    for (int c = 0; c < 8; c++)
                        acc[r][c] = fmaf(xf[r], yf[c], acc[r][c]);
            }
            __syncthreads();
        }

        // scale into log2 domain
#pragma unroll
        for (int r = 0; r < 8; r++)
#pragma unroll
            for (int c = 0; c < 8; c++) acc[r][c] *= SCALE_LOG2;

        // capture diagonal if this tile sits on it
        if (col0 == row0 && tx == ty) {
#pragma unroll
            for (int r = 0; r < 8; r++)
                g_pos[row0 + ty * 8 + r] = acc[r][r];
        }

        // online logsumexp update (16 lanes share each row; lanes of the same
        // ty are contiguous 16-lane halves of a warp, so xor-shuffles 1..8 stay in-group)
#pragma unroll
        for (int r = 0; r < 8; r++) {
            float tmax = acc[r][0];
#pragma unroll
            for (int c = 1; c < 8; c++) tmax = fmaxf(tmax, acc[r][c]);
#pragma unroll
            for (int o = 8; o >= 1; o >>= 1)
                tmax = fmaxf(tmax, __shfl_xor_sync(0xffffffffu, tmax, o));

            const float nm = fmaxf(m[r], tmax);
            float sum = 0.0f;
#pragma unroll
            for (int c = 0; c < 8; c++) sum += ex2f(acc[r][c] - nm);
#pragma unroll
            for (int o = 8; o >= 1; o >>= 1)
                sum += __shfl_xor_sync(0xffffffffu, sum, o);

            l[r] = l[r] * ex2f(m[r] - nm) + sum;
            m[r] = nm;
        }
    }

    if (tx == 0) {
#pragma unroll
        for (int r = 0; r < 8; r++) {
            g_m[split][row0 + ty * 8 + r] = m[r];
            g_l[split][row0 + ty * 8 + r] = l[r];
        }
    }
}

__global__ void cl_combine_kernel() {
    const int i = blockIdx.x * blockDim.x + threadIdx.x;
    if (i >= NROWS) return;
    float M = g_m[0][i];
#pragma unroll
    for (int s = 1; s < COLSPLIT; s++) M = fmaxf(M, g_m[s][i]);
    float L = 0.0f;
#pragma unroll
    for (int s = 0; s < COLSPLIT; s++) L += g_l[s][i] * ex2f(g_m[s][i] - M);
    g_row[i] = M + __log2f(L) - g_pos[i];
}

__global__ void cl_reduce_kernel(float* __restrict__ out) {
    __shared__ float sh[256];
    float s = 0.0f;
    for (int i = threadIdx.x; i < NROWS; i += 256) s += g_row[i];
    sh[threadIdx.x] = s;
    __syncthreads();
    for (int o = 128; o > 0; o >>= 1) {
        if (threadIdx.x < o) sh[threadIdx.x] += sh[threadIdx.x + o];
        __syncthreads();
    }
    if (threadIdx.x == 0) out[0] = sh[0] * LN2;
}

extern "C" void kernel_launch(void* const* d_in, const int* in_sizes, int n_in,
                              void* d_out, int out_size) {
    const float* X = (const float*)d_in[0];
    const float* Y = (const float*)d_in[1];
    float* out = (float*)d_out;

    dim3 grid(NROWS / BM, COLSPLIT);
    cl_main_kernel<<<grid, 256>>>(X, Y);
    cl_combine_kernel<<<NROWS / 256, 256>>>();
    cl_reduce_kernel<<<1, 256>>>(out);
}

// round 3
// speedup vs baseline: 4.0190x; 4.0190x over previous
#include <cuda_runtime.h>
#include <cuda_bf16.h>
#include <math.h>
#include <stdint.h>

// ContrastiveLoss: loss = sum_i [ logsumexp_j(X_i.Y_j/T) - X_i.Y_i/T ]
// N=8192, C=512, T=0.07. tf32 mma.sync GEMM (base sm_103 target - no tcgen05)
// fused with online logsumexp in log2 domain.

#define NTOT 8192
#define CDIM 512
#define ROWB 128                 // rows per CTA
#define COLSPLIT 8
#define COLS_PER_SPLIT (NTOT / COLSPLIT)   // 1024
#define NTILES (COLS_PER_SPLIT / 128)      // 8 col tiles of 128
#define KITER  (CDIM / 32)                 // 16 k-iters per tile
#define NSTEPS (NTILES * KITER)            // 128 flat steps
#define NPART  (COLSPLIT * 4)              // 32 column partitions (split x warpN)

#define PADK 36                            // padded floats per smem row (32 + 4)
#define XTILE_BYTES (128 * PADK * 4)       // 18432
#define STAGE_BYTES (2 * XTILE_BYTES)      // X + Y
#define SMEM_TOTAL  (2 * STAGE_BYTES)      // double buffer: 73728

#define SCALE_LOG2 (14.285714285714286f * 1.4426950408889634f)
#define LN2 0.6931471805599453f

// -------- scratch (device globals; no allocation allowed) --------
__device__ __align__(16) float g_Xr[NTOT * CDIM];   // tf32-rounded, row-major
__device__ __align__(16) float g_Yr[NTOT * CDIM];
__device__ float g_m[NPART][NTOT];
__device__ float g_l[NPART][NTOT];
__device__ float g_pos[NTOT];
__device__ float g_row[NTOT];

__device__ __forceinline__ float ex2f(float x) {
    float y; asm("ex2.approx.ftz.f32 %0, %1;" : "=f"(y) : "f"(x)); return y;
}
__device__ __forceinline__ uint32_t smem_to_u32(const void* p) {
    uint32_t a;
    asm("{ .reg .u64 t; cvta.to.shared.u64 t, %1; cvt.u32.u64 %0, t; }" : "=r"(a) : "l"(p));
    return a;
}
__device__ __forceinline__ void cp_async16(uint32_t dst, const void* src) {
    asm volatile("cp.async.ca.shared.global [%0], [%1], 16;" :: "r"(dst), "l"(src) : "memory");
}
#define CP_COMMIT() asm volatile("cp.async.commit_group;" ::: "memory")
#define CP_WAIT_1() asm volatile("cp.async.wait_group 1;" ::: "memory")
#define CP_WAIT_0() asm volatile("cp.async.wait_group 0;" ::: "memory")

__device__ __forceinline__ void mma_tf32(float* c, const uint32_t* a, const uint32_t* b) {
    asm volatile(
        "mma.sync.aligned.m16n8k8.row.col.f32.tf32.tf32.f32 "
        "{%0,%1,%2,%3}, {%4,%5,%6,%7}, {%8,%9}, {%0,%1,%2,%3};"
        : "+f"(c[0]), "+f"(c[1]), "+f"(c[2]), "+f"(c[3])
        : "r"(a[0]), "r"(a[1]), "r"(a[2]), "r"(a[3]), "r"(b[0]), "r"(b[1]));
}

// -------- pre-kernel: round inputs to tf32 (RNA, zero-mean error) --------
__global__ void __launch_bounds__(256)
cl_pre_kernel(const float* __restrict__ X, const float* __restrict__ Y) {
    const uint32_t gid = blockIdx.x * 256u + threadIdx.x;
    const uint32_t per_tensor = (NTOT * CDIM) / 4;
    const float* src = (gid < per_tensor) ? X : Y;
    float* dst = (gid < per_tensor) ? g_Xr : g_Yr;
    const uint32_t i4 = (gid < per_tensor) ? gid : (gid - per_tensor);
    float4 v = *reinterpret_cast<const float4*>(src + (size_t)i4 * 4);
    uint4 o;
    asm("cvt.rna.tf32.f32 %0, %1;" : "=r"(o.x) : "f"(v.x));
    asm("cvt.rna.tf32.f32 %0, %1;" : "=r"(o.y) : "f"(v.y));
    asm("cvt.rna.tf32.f32 %0, %1;" : "=r"(o.z) : "f"(v.z));
    asm("cvt.rna.tf32.f32 %0, %1;" : "=r"(o.w) : "f"(v.w));
    *reinterpret_cast<uint4*>(dst + (size_t)i4 * 4) = o;
}

// -------- main kernel --------
__global__ void __launch_bounds__(256, 2)
cl_mma_kernel() {
    extern __shared__ __align__(16) char smem[];
    const uint32_t sb = smem_to_u32(smem);
    const uint32_t* smf = reinterpret_cast<const uint32_t*>(smem);

    const int tid = threadIdx.x;
    const int wid = tid >> 5;
    const int lane = tid & 31;
    const int g = lane >> 2;          // fragment group id 0..7
    const int q = lane & 3;           // fragment quad id 0..3
    const int warpM = wid >> 2;       // 0..1  (64-row half)
    const int warpN = wid & 3;        // 0..3  (32-col stripe)

    const int rowblk = blockIdx.x >> 3;
    const int split = blockIdx.x & 7;
    const int row0 = rowblk * ROWB;
    const int colbase = split * COLS_PER_SPLIT;

    // ---- stage loader: step -> (tile, k-iter) ----
    auto load_stage = [&](int step, int buf) {
        const int t = step >> 4;
        const int k0 = (step & 15) * 32;
        const int col0 = colbase + t * 128;
        const uint32_t xd = sb + buf * STAGE_BYTES;
        const uint32_t yd = xd + XTILE_BYTES;
#pragma unroll
        for (int i = 0; i < 4; i++) {
            const int idx = tid + i * 256;       // 0..1023
            const int row = idx >> 3;
            const int u = idx & 7;
            cp_async16(xd + row * (PADK * 4) + u * 16,
                       g_Xr + (size_t)(row0 + row) * CDIM + k0 + u * 4);
            cp_async16(yd + row * (PADK * 4) + u * 16,
                       g_Yr + (size_t)(col0 + row) * CDIM + k0 + u * 4);
        }
        CP_COMMIT();
    };

    float acc[4][4][4];
    float m[8], l[8];
#pragma unroll
    for (int r = 0; r < 8; r++) { m[r] = -INFINITY; l[r] = 0.0f; }

    load_stage(0, 0);

    for (int step = 0; step < NSTEPS; step++) {
        const int buf = step & 1;

        if ((step & 15) == 0) {
#pragma unroll
            for (int mb = 0; mb < 4; mb++)
#pragma unroll
                for (int nb = 0; nb < 4; nb++)
#pragma unroll
                    for (int c = 0; c < 4; c++) acc[mb][nb][c] = 0.0f;
        }

        if (step + 1 < NSTEPS) { load_stage(step + 1, buf ^ 1); CP_WAIT_1(); }
        else CP_WAIT_0();
        __syncthreads();

        // ---- compute 32 k on this stage ----
        const uint32_t* Xb = smf + (buf * STAGE_BYTES) / 4;
        const uint32_t* Yb = Xb + XTILE_BYTES / 4;
#pragma unroll
        for (int s = 0; s < 4; s++) {
            const int kb = s * 8;
            uint32_t a[4][4], b[4][2];
#pragma unroll
            for (int mb = 0; mb < 4; mb++) {
                const int r0 = warpM * 64 + mb * 16 + g;
                a[mb][0] = Xb[r0 * PADK + kb + q];
                a[mb][1] = Xb[(r0 + 8) * PADK + kb + q];
                a[mb][2] = Xb[r0 * PADK + kb + q + 4];
                a[mb][3] = Xb[(r0 + 8) * PADK + kb + q + 4];
            }
#pragma unroll
            for (int nb = 0; nb < 4; nb++) {
                const int cn = warpN * 32 + nb * 8 + g;
                b[nb][0] = Yb[cn * PADK + kb + q];
                b[nb][1] = Yb[cn * PADK + kb + q + 4];
            }
#pragma unroll
            for (int mb = 0; mb < 4; mb++)
#pragma unroll
                for (int nb = 0; nb < 4; nb++)
                    mma_tf32(acc[mb][nb], a[mb], b[nb]);
        }
        __syncthreads();

        // ---- fused epilogue at tile end (register-only) ----
        if ((step & 15) == 15) {
            const int t = step >> 4;
            const int col0 = colbase + t * 128 + warpN * 32;
#pragma unroll
            for (int mb = 0; mb < 4; mb++) {
#pragma unroll
                for (int pr = 0; pr < 2; pr++) {
                    const int ri = mb * 2 + pr;
                    const int grow = row0 + warpM * 64 + mb * 16 + g + pr * 8;
                    float v[8];
                    float tmax = -INFINITY;
#pragma unroll
                    for (int nb = 0; nb < 4; nb++) {
                        v[2 * nb] = acc[mb][nb][2 * pr] * SCALE_LOG2;
                        v[2 * nb + 1] = acc[mb][nb][2 * pr + 1] * SCALE_LOG2;
                        tmax = fmaxf(tmax, fmaxf(v[2 * nb], v[2 * nb + 1]));
                    }
                    tmax = fmaxf(tmax, __shfl_xor_sync(0xffffffffu, tmax, 1));
                    tmax = fmaxf(tmax, __shfl_xor_sync(0xffffffffu, tmax, 2));
                    const float nm = fmaxf(m[ri], tmax);
                    float sum = 0.0f;
#pragma unroll
                    for (int nb = 0; nb < 4; nb++) {
                        const int gc = col0 + nb * 8 + q * 2;
                        sum += ex2f(v[2 * nb] - nm) + ex2f(v[2 * nb + 1] - nm);
                        if (gc == grow) g_pos[grow] = v[2 * nb];
                        if (gc + 1 == grow) g_pos[grow] = v[2 * nb + 1];
                    }
                    sum += __shfl_xor_sync(0xffffffffu, sum, 1);
                    sum += __shfl_xor_sync(0xffffffffu, sum, 2);
                    l[ri] = l[ri] * ex2f(m[ri] - nm) + sum;
                    m[ri] = nm;
                }
            }
        }
    }

    // ---- write per-partition partials ----
    if (q == 0) {
        const int sp = split * 4 + warpN;
#pragma unroll
        for (int mb = 0; mb < 4; mb++)
#pragma unroll
            for (int pr = 0; pr < 2; pr++) {
                const int grow = row0 + warpM * 64 + mb * 16 + g + pr * 8;
                g_m[sp][grow] = m[mb * 2 + pr];
                g_l[sp][grow] = l[mb * 2 + pr];
            }
    }
}

// -------- combine + reduce --------
__global__ void cl_combine_kernel() {
    const int i = blockIdx.x * blockDim.x + threadIdx.x;
    if (i >= NTOT) return;
    float M = g_m[0][i];
#pragma unroll
    for (int s = 1; s < NPART; s++) M = fmaxf(M, g_m[s][i]);
    float L = 0.0f;
#pragma unroll
    for (int s = 0; s < NPART; s++) L += g_l[s][i] * ex2f(g_m[s][i] - M);
    g_row[i] = M + __log2f(L) - g_pos[i];
}

__global__ void cl_reduce_kernel(float* __restrict__ out) {
    __shared__ float sh[256];
    float s = 0.0f;
    for (int i = threadIdx.x; i < NTOT; i += 256) s += g_row[i];
    sh[threadIdx.x] = s;
    __syncthreads();
    for (int o = 128; o > 0; o >>= 1) {
        if (threadIdx.x < o) sh[threadIdx.x] += sh[threadIdx.x + o];
        __syncthreads();
    }
    if (threadIdx.x == 0) out[0] = sh[0] * LN2;
}

extern "C" void kernel_launch(void* const* d_in, const int* in_sizes, int n_in,
                              void* d_out, int out_size) {
    const float* X = (const float*)d_in[0];
    const float* Y = (const float*)d_in[1];
    float* out = (float*)d_out;

    cudaFuncSetAttribute(cl_mma_kernel, cudaFuncAttributeMaxDynamicSharedMemorySize, SMEM_TOTAL);

    cl_pre_kernel<<<(2 * (NTOT * CDIM) / 4) / 256, 256>>>(X, Y);
    cl_mma_kernel<<<64 * COLSPLIT, 256, SMEM_TOTAL>>>();
    cl_combine_kernel<<<NTOT / 256, 256>>>();
    cl_reduce_kernel<<<1, 256>>>(out);
}

// round 4
// speedup vs baseline: 4.6132x; 1.1479x over previous
#include <cuda_runtime.h>
#include <cuda_bf16.h>
#include <math.h>
#include <stdint.h>

// ContrastiveLoss: loss = sum_i [ logsumexp_j(X_i.Y_j/T) - X_i.Y_i/T ]
// N=8192, C=512, T=0.07. tf32 mma.sync GEMM, fragment-major prepacked operands,
// 3-stage cp.async pipeline, fused online logsumexp (log2 domain).

#define NTOT 8192
#define CDIM 512
#define ROWB 128
#define COLSPLIT 8
#define COLS_PER_SPLIT (NTOT / COLSPLIT)   // 1024
#define NTILES (COLS_PER_SPLIT / 128)      // 8
#define NSTEPS (NTILES * 16)               // 128 (k-step = 32 = one k-chunk)
#define NPART  (COLSPLIT * 4)

#define XSTAGE_BYTES 16384
#define STAGE_BYTES  32768                 // X 16KB + Y 16KB
#define NSTAGE 3
#define SMEM_TOTAL (NSTAGE * STAGE_BYTES)  // 98304

#define PLANE_FLOATS 262144                // floats per k-chunk plane (1MB)

#define SCALE_LOG2 (14.285714285714286f * 1.4426950408889634f)
#define LN2 0.6931471805599453f

// -------- scratch (device globals; no allocation allowed) --------
__device__ __align__(16) float g_Xa[NTOT * CDIM];   // A-fragment-major, tf32-rounded
__device__ __align__(16) float g_Yb[NTOT * CDIM];   // B-fragment-major, tf32-rounded
__device__ float g_m[NPART][NTOT];
__device__ float g_l[NPART][NTOT];
__device__ float g_pos[NTOT];
__device__ float g_row[NTOT];

__device__ __forceinline__ float ex2f(float x) {
    float y; asm("ex2.approx.ftz.f32 %0, %1;" : "=f"(y) : "f"(x)); return y;
}
__device__ __forceinline__ uint32_t smem_to_u32(const void* p) {
    uint32_t a;
    asm("{ .reg .u64 t; cvta.to.shared.u64 t, %1; cvt.u32.u64 %0, t; }" : "=r"(a) : "l"(p));
    return a;
}
__device__ __forceinline__ void cp_async16(uint32_t dst, const void* src) {
    asm volatile("cp.async.ca.shared.global [%0], [%1], 16;" :: "r"(dst), "l"(src) : "memory");
}
#define CP_COMMIT() asm volatile("cp.async.commit_group;" ::: "memory")
#define CP_WAIT_2() asm volatile("cp.async.wait_group 2;" ::: "memory")

__device__ __forceinline__ uint32_t tf32r(float x) {
    uint32_t r; asm("cvt.rna.tf32.f32 %0, %1;" : "=r"(r) : "f"(x)); return r;
}

__device__ __forceinline__ void mma_tf32(float* c, const uint4 a, uint32_t b0, uint32_t b1) {
    asm volatile(
        "mma.sync.aligned.m16n8k8.row.col.f32.tf32.tf32.f32 "
        "{%0,%1,%2,%3}, {%4,%5,%6,%7}, {%8,%9}, {%0,%1,%2,%3};"
        : "+f"(c[0]), "+f"(c[1]), "+f"(c[2]), "+f"(c[3])
        : "r"(a.x), "r"(a.y), "r"(a.z), "r"(a.w), "r"(b0), "r"(b1));
}

// -------- pre-kernel: tf32 round + fragment-major packing --------
// A fragment (kc, rb, s, lane(g,q)) = { X[rb*16+g][kc*32+s*8+q], X[+8][..q],
//                                       X[..][..q+4], X[+8][..q+4] }
// B fragment (kc, cb, kp, lane(g,q)) = { Y[cb*8+g][kc*32+kp*16+q],   [..q+4],
//                                        Y[..][..+8+q],              [..+12+q] }
__global__ void __launch_bounds__(256)
cl_pre_kernel(const float* __restrict__ X, const float* __restrict__ Y) {
    const uint32_t gid = blockIdx.x * 256u + threadIdx.x;
    const uint32_t NFRAG = (NTOT * CDIM) / 4;   // 1048576 per tensor
    if (gid < NFRAG) {
        const uint32_t fid = gid;
        const uint32_t lane = fid & 31, s = (fid >> 5) & 3, rb = (fid >> 7) & 511, kc = fid >> 16;
        const uint32_t g = lane >> 2, q = lane & 3;
        const size_t base = (size_t)(rb * 16 + g) * CDIM + kc * 32 + s * 8 + q;
        uint4 o;
        o.x = tf32r(X[base]);
        o.y = tf32r(X[base + 8 * CDIM]);
        o.z = tf32r(X[base + 4]);
        o.w = tf32r(X[base + 8 * CDIM + 4]);
        *reinterpret_cast<uint4*>(g_Xa + (size_t)fid * 4) = o;
    } else {
        const uint32_t fid = gid - NFRAG;
        const uint32_t lane = fid & 31, kp = (fid >> 5) & 1, cb = (fid >> 6) & 1023, kc = fid >> 16;
        const uint32_t g = lane >> 2, q = lane & 3;
        const size_t base = (size_t)(cb * 8 + g) * CDIM + kc * 32 + kp * 16 + q;
        uint4 o;
        o.x = tf32r(Y[base]);
        o.y = tf32r(Y[base + 4]);
        o.z = tf32r(Y[base + 8]);
        o.w = tf32r(Y[base + 12]);
        *reinterpret_cast<uint4*>(g_Yb + (size_t)fid * 4) = o;
    }
}

// -------- main kernel --------
__global__ void __launch_bounds__(256, 2)
cl_mma_kernel() {
    extern __shared__ __align__(16) char smem[];
    const uint32_t sb = smem_to_u32(smem);
    const uint4* sm4 = reinterpret_cast<const uint4*>(smem);

    const int tid = threadIdx.x;
    const int wid = tid >> 5;
    const int lane = tid & 31;
    const int g = lane >> 2;
    const int q = lane & 3;
    const int warpM = wid >> 2;       // 0..1
    const int warpN = wid & 3;        // 0..3

    const int rowblk = blockIdx.x >> 3;
    const int split = blockIdx.x & 7;
    const int row0 = rowblk * ROWB;
    const int colbase = split * COLS_PER_SPLIT;

    // stage loader: step -> (tile t, k-chunk kc); 16KB X + 16KB Y, 8 cp.async/thread
    auto load_stage = [&](int step, int buf) {
        if (step < NSTEPS) {
            const int t = step >> 4;
            const int kc = step & 15;
            const float* xsrc = g_Xa + (size_t)kc * PLANE_FLOATS + (size_t)(row0 >> 4) * 512;
            const float* ysrc = g_Yb + (size_t)kc * PLANE_FLOATS + (size_t)((colbase + t * 128) >> 3) * 256;
            const uint32_t xd = sb + buf * STAGE_BYTES;
            const uint32_t yd = xd + XSTAGE_BYTES;
#pragma unroll
            for (int i = 0; i < 4; i++) {
                const int c = tid + i * 256;   // 0..1023 16B-chunks
                cp_async16(xd + c * 16, xsrc + c * 4);
                cp_async16(yd + c * 16, ysrc + c * 4);
            }
        }
        CP_COMMIT();
    };

    float acc[4][4][4];
    float m[8], l[8];
#pragma unroll
    for (int r = 0; r < 8; r++) { m[r] = -INFINITY; l[r] = 0.0f; }

    load_stage(0, 0);
    load_stage(1, 1);

    for (int step = 0; step < NSTEPS; step++) {
        const int buf = step % NSTAGE;

        if ((step & 15) == 0) {
#pragma unroll
            for (int mb = 0; mb < 4; mb++)
#pragma unroll
                for (int nb = 0; nb < 4; nb++)
#pragma unroll
                    for (int c = 0; c < 4; c++) acc[mb][nb][c] = 0.0f;
        }

        load_stage(step + 2, (step + 2) % NSTAGE);
        CP_WAIT_2();
        __syncthreads();

        // fragment views for this stage
        const uint4* Xf = sm4 + (buf * STAGE_BYTES) / 16;          // [rb_local(8)][s(4)][lane(32)]
        const uint4* Yf = Xf + XSTAGE_BYTES / 16;                  // [cb_local(16)][kp(2)][lane(32)]

#pragma unroll
        for (int kp = 0; kp < 2; kp++) {
            uint4 bq[4];
#pragma unroll
            for (int nb = 0; nb < 4; nb++)
                bq[nb] = Yf[((warpN * 4 + nb) * 2 + kp) * 32 + lane];
#pragma unroll
            for (int ss = 0; ss < 2; ss++) {
                const int s = kp * 2 + ss;
#pragma unroll
                for (int mb = 0; mb < 4; mb++) {
                    const uint4 av = Xf[((warpM * 4 + mb) * 4 + s) * 32 + lane];
#pragma unroll
                    for (int nb = 0; nb < 4; nb++) {
                        if (ss == 0) mma_tf32(acc[mb][nb], av, bq[nb].x, bq[nb].y);
                        else         mma_tf32(acc[mb][nb], av, bq[nb].z, bq[nb].w);
                    }
                }
            }
        }

        // fused epilogue at tile end (register-only)
        if ((step & 15) == 15) {
            const int t = step >> 4;
            const int col0 = colbase + t * 128 + warpN * 32;
#pragma unroll
            for (int mb = 0; mb < 4; mb++) {
#pragma unroll
                for (int pr = 0; pr < 2; pr++) {
                    const int ri = mb * 2 + pr;
                    const int grow = row0 + warpM * 64 + mb * 16 + g + pr * 8;
                    float v[8];
                    float tmax = -INFINITY;
#pragma unroll
                    for (int nb = 0; nb < 4; nb++) {
                        v[2 * nb] = acc[mb][nb][2 * pr] * SCALE_LOG2;
                        v[2 * nb + 1] = acc[mb][nb][2 * pr + 1] * SCALE_LOG2;
                        tmax = fmaxf(tmax, fmaxf(v[2 * nb], v[2 * nb + 1]));
                    }
                    tmax = fmaxf(tmax, __shfl_xor_sync(0xffffffffu, tmax, 1));
                    tmax = fmaxf(tmax, __shfl_xor_sync(0xffffffffu, tmax, 2));
                    const float nm = fmaxf(m[ri], tmax);
                    float sum = 0.0f;
#pragma unroll
                    for (int nb = 0; nb < 4; nb++) {
                        const int gc = col0 + nb * 8 + q * 2;
                        sum += ex2f(v[2 * nb] - nm) + ex2f(v[2 * nb + 1] - nm);
                        if (gc == grow) g_pos[grow] = v[2 * nb];
                        if (gc + 1 == grow) g_pos[grow] = v[2 * nb + 1];
                    }
                    sum += __shfl_xor_sync(0xffffffffu, sum, 1);
                    sum += __shfl_xor_sync(0xffffffffu, sum, 2);
                    l[ri] = l[ri] * ex2f(m[ri] - nm) + sum;
                    m[ri] = nm;
                }
            }
        }
    }

    if (q == 0) {
        const int sp = split * 4 + warpN;
#pragma unroll
        for (int mb = 0; mb < 4; mb++)
#pragma unroll
            for (int pr = 0; pr < 2; pr++) {
                const int grow = row0 + warpM * 64 + mb * 16 + g + pr * 8;
                g_m[sp][grow] = m[mb * 2 + pr];
                g_l[sp][grow] = l[mb * 2 + pr];
            }
    }
}

// -------- combine + reduce --------
__global__ void cl_combine_kernel() {
    const int i = blockIdx.x * blockDim.x + threadIdx.x;
    if (i >= NTOT) return;
    float M = g_m[0][i];
#pragma unroll
    for (int s = 1; s < NPART; s++) M = fmaxf(M, g_m[s][i]);
    float L = 0.0f;
#pragma unroll
    for (int s = 0; s < NPART; s++) L += g_l[s][i] * ex2f(g_m[s][i] - M);
    g_row[i] = M + __log2f(L) - g_pos[i];
}

__global__ void cl_reduce_kernel(float* __restrict__ out) {
    __shared__ float sh[256];
    float s = 0.0f;
    for (int i = threadIdx.x; i < NTOT; i += 256) s += g_row[i];
    sh[threadIdx.x] = s;
    __syncthreads();
    for (int o = 128; o > 0; o >>= 1) {
        if (threadIdx.x < o) sh[threadIdx.x] += sh[threadIdx.x + o];
        __syncthreads();
    }
    if (threadIdx.x == 0) out[0] = sh[0] * LN2;
}

extern "C" void kernel_launch(void* const* d_in, const int* in_sizes, int n_in,
                              void* d_out, int out_size) {
    const float* X = (const float*)d_in[0];
    const float* Y = (const float*)d_in[1];
    float* out = (float*)d_out;

    cudaFuncSetAttribute(cl_mma_kernel, cudaFuncAttributeMaxDynamicSharedMemorySize, SMEM_TOTAL);

    cl_pre_kernel<<<(2 * (NTOT * CDIM) / 4) / 256, 256>>>(X, Y);
    cl_mma_kernel<<<64 * COLSPLIT, 256, SMEM_TOTAL>>>();
    cl_combine_kernel<<<NTOT / 256, 256>>>();
    cl_reduce_kernel<<<1, 256>>>(out);
}